// round 16
// baseline (speedup 1.0000x reference)
#include <cuda_runtime.h>
#include <cuda_bf16.h>
#include <cstdint>
#include <math.h>

// ---------------- problem constants ----------------
#define NB 32
#define HH 56
#define WW 56
#define CD 256
#define TOK (NB*HH*WW)          // 100352 tokens
#define HEADS 8
#define HDIM 32
#define HID 1024
#define WS 7
#define NWIN (TOK/(WS*WS))      // 2048 windows

typedef __nv_bfloat16 bf16;
typedef __nv_bfloat162 bf162;

// ---------------- scratch (static device globals; no runtime alloc) -------
__device__ __align__(16) bf16  g_y   [(size_t)TOK * CD];
__device__ __align__(16) bf16  g_qkv [(size_t)TOK * 3 * CD];
__device__ __align__(16) bf16  g_o   [(size_t)TOK * CD];
__device__ __align__(16) float g_x1  [(size_t)TOK * CD];
__device__ __align__(16) bf16  g_z   [(size_t)TOK * CD];
__device__ __align__(16) bf16  g_h1  [(size_t)TOK * HID];
__device__ __align__(16) float g_bias[8 * 64 * 64];
__device__ __align__(16) bf16  g_wq[3 * CD * CD];
__device__ __align__(16) bf16  g_wp[CD * CD];
__device__ __align__(16) bf16  g_w1[HID * CD];
__device__ __align__(16) bf16  g_w2[CD * HID];

// ---------------- fused preprocessing + LN1 ---------------------------------
#define PRE_BLKS 896
__global__ __launch_bounds__(256) void pre_ln1(const float* __restrict__ qkv_w,
                                               const float* __restrict__ proj_w,
                                               const float* __restrict__ ffn_w1,
                                               const float* __restrict__ ffn_w2,
                                               const float* __restrict__ table,
                                               bf16* __restrict__ wq, bf16* __restrict__ wp,
                                               bf16* __restrict__ w1, bf16* __restrict__ w2,
                                               float* __restrict__ bfull,
                                               const float* __restrict__ x,
                                               const float* __restrict__ lng,
                                               const float* __restrict__ lnb,
                                               bf16* __restrict__ y) {
    if (blockIdx.x < PRE_BLKS) {
        int i = blockIdx.x * 256 + threadIdx.x;
        if (i < 196608) {
            const float* src;
            bf16* dst;
            int j;
            if (i < 49152)        { src = qkv_w;  dst = wq; j = i; }
            else if (i < 65536)   { src = proj_w; dst = wp; j = i - 49152; }
            else if (i < 131072)  { src = ffn_w1; dst = w1; j = i - 65536; }
            else                  { src = ffn_w2; dst = w2; j = i - 131072; }
            float4 v = ((const float4*)src)[j];
            *(bf162*)&dst[j * 4]     = __floats2bfloat162_rn(v.x, v.y);
            *(bf162*)&dst[j * 4 + 2] = __floats2bfloat162_rn(v.z, v.w);
        } else if (i < 229376) {
            int idx = i - 196608;
            int h = idx >> 12;
            int r = (idx >> 6) & 63;
            int c = idx & 63;
            float v;
            if (c >= 49) v = -1e30f;
            else if (r >= 49) v = 0.f;
            else {
                int ri = r / 7, ci = r % 7, rj = c / 7, cj = c % 7;
                int rel = (ri - rj + 6) * 13 + (ci - cj + 6);
                v = table[rel * 8 + h];
            }
            bfull[idx] = v;
        }
        return;
    }
    int warp = ((blockIdx.x - PRE_BLKS) * 256 + threadIdx.x) >> 5;
    int lane = threadIdx.x & 31;
    if (warp >= TOK) return;
    const float* row = x + (size_t)warp * CD;
    float v[8];
    *(float4*)&v[0] = ((const float4*)row)[lane * 2];
    *(float4*)&v[4] = ((const float4*)row)[lane * 2 + 1];
    float s = 0.f;
#pragma unroll
    for (int k = 0; k < 8; k++) s += v[k];
#pragma unroll
    for (int o = 16; o; o >>= 1) s += __shfl_xor_sync(0xffffffffu, s, o);
    float mean = s * (1.f / 256.f);
    float ss = 0.f;
#pragma unroll
    for (int k = 0; k < 8; k++) { float d = v[k] - mean; ss += d * d; }
#pragma unroll
    for (int o = 16; o; o >>= 1) ss += __shfl_xor_sync(0xffffffffu, ss, o);
    float inv = rsqrtf(ss * (1.f / 256.f) + 1e-5f);
    float gg[8], bb[8];
    *(float4*)&gg[0] = ((const float4*)lng)[lane * 2];
    *(float4*)&gg[4] = ((const float4*)lng)[lane * 2 + 1];
    *(float4*)&bb[0] = ((const float4*)lnb)[lane * 2];
    *(float4*)&bb[4] = ((const float4*)lnb)[lane * 2 + 1];
    bf16* orow = y + (size_t)warp * CD + lane * 8;
#pragma unroll
    for (int k = 0; k < 4; k++) {
        float v0 = (v[2*k]   - mean) * inv * gg[2*k]   + bb[2*k];
        float v1 = (v[2*k+1] - mean) * inv * gg[2*k+1] + bb[2*k+1];
        *(bf162*)&orow[2*k] = __floats2bfloat162_rn(v0, v1);
    }
}

// ---------------- mma / cp.async / ldmatrix helpers ------------------------
__device__ __forceinline__ void mma_bf16(float* c, const unsigned* a, const unsigned* b) {
    asm volatile(
        "mma.sync.aligned.m16n8k16.row.col.f32.bf16.bf16.f32 "
        "{%0,%1,%2,%3}, {%4,%5,%6,%7}, {%8,%9}, {%0,%1,%2,%3};\n"
        : "+f"(c[0]), "+f"(c[1]), "+f"(c[2]), "+f"(c[3])
        : "r"(a[0]), "r"(a[1]), "r"(a[2]), "r"(a[3]), "r"(b[0]), "r"(b[1]));
}

__device__ __forceinline__ void cpa16(void* smem_dst, const void* gsrc) {
    unsigned s = (unsigned)__cvta_generic_to_shared(smem_dst);
    asm volatile("cp.async.cg.shared.global [%0], [%1], 16;\n" :: "r"(s), "l"(gsrc));
}

__device__ __forceinline__ void cpa16z(void* smem_dst, const void* gsrc, unsigned srcsz) {
    unsigned s = (unsigned)__cvta_generic_to_shared(smem_dst);
    asm volatile("cp.async.cg.shared.global [%0], [%1], 16, %2;\n"
                 :: "r"(s), "l"(gsrc), "r"(srcsz));
}

__device__ __forceinline__ void ldsm4(unsigned& r0, unsigned& r1,
                                      unsigned& r2, unsigned& r3, const void* p) {
    unsigned a = (unsigned)__cvta_generic_to_shared(p);
    asm volatile("ldmatrix.sync.aligned.m8n8.x4.shared.b16 {%0,%1,%2,%3}, [%4];"
                 : "=r"(r0), "=r"(r1), "=r"(r2), "=r"(r3) : "r"(a));
}

__device__ __forceinline__ void ldsm4t(unsigned& r0, unsigned& r1,
                                       unsigned& r2, unsigned& r3, const void* p) {
    unsigned a = (unsigned)__cvta_generic_to_shared(p);
    asm volatile("ldmatrix.sync.aligned.m8n8.x4.trans.shared.b16 {%0,%1,%2,%3}, [%4];"
                 : "=r"(r0), "=r"(r1), "=r"(r2), "=r"(r3) : "r"(a));
}

// ---------------- bf16 GEMM (R7/R12-proven structure, FROZEN) --------------
enum { EP_BIAS = 0, EP_BIAS_RES = 1, EP_BIAS_GELU = 2 };

#define SP40 40   // smem pitch (halves): 8 rows @ stride 20 banks partition 32 banks

template <int EP, typename OutT>
__global__ __launch_bounds__(256) void hgemm(const bf16* __restrict__ A,
                                             const bf16* __restrict__ W,
                                             const float* __restrict__ bias,
                                             const float* __restrict__ res,
                                             OutT* __restrict__ C,
                                             int M, int N, int K) {
    __shared__ bf16 As[2][128][SP40];
    __shared__ bf16 Bs[2][128][SP40];

    int tid = threadIdx.x;
    int bm = blockIdx.y * 128;
    int bn = blockIdx.x * 128;
    int warp = tid >> 5, lane = tid & 31;
    int g = lane >> 2, tig = lane & 3;
    int warpM = warp >> 2;
    int warpN = warp & 3;
    int l16 = lane & 15;
    int lhi = (lane >> 4) * 8;

    int lrow = tid >> 2;
    int lcol = (tid & 3) * 8;

    const bf16* Aptr = A + (size_t)(bm + lrow) * K + lcol;
    const bf16* Wptr = W + (size_t)(bn + lrow) * K + lcol;

    float acc[4][4][4];
#pragma unroll
    for (int i = 0; i < 4; i++)
#pragma unroll
        for (int j = 0; j < 4; j++)
#pragma unroll
            for (int t = 0; t < 4; t++) acc[i][j][t] = 0.f;

    cpa16(&As[0][lrow][lcol],      Aptr);
    cpa16(&As[0][lrow + 64][lcol], Aptr + (size_t)64 * K);
    cpa16(&Bs[0][lrow][lcol],      Wptr);
    cpa16(&Bs[0][lrow + 64][lcol], Wptr + (size_t)64 * K);
    asm volatile("cp.async.commit_group;\n");

    int niter = K / 32;
    for (int it = 0; it < niter; it++) {
        int cur = it & 1;
        if (it + 1 < niter) {
            int k0 = (it + 1) * 32;
            int nxt = cur ^ 1;
            cpa16(&As[nxt][lrow][lcol],      Aptr + k0);
            cpa16(&As[nxt][lrow + 64][lcol], Aptr + (size_t)64 * K + k0);
            cpa16(&Bs[nxt][lrow][lcol],      Wptr + k0);
            cpa16(&Bs[nxt][lrow + 64][lcol], Wptr + (size_t)64 * K + k0);
            asm volatile("cp.async.commit_group;\n");
            asm volatile("cp.async.wait_group 1;\n");
        } else {
            asm volatile("cp.async.wait_group 0;\n");
        }
        __syncthreads();

#pragma unroll
        for (int s = 0; s < 2; s++) {
            int kk0 = s * 16;
            unsigned af[4][4], bfr[4][2];
#pragma unroll
            for (int mt = 0; mt < 4; mt++) {
                int m = warpM * 64 + mt * 16 + l16;
                ldsm4(af[mt][0], af[mt][1], af[mt][2], af[mt][3],
                      &As[cur][m][kk0 + lhi]);
            }
#pragma unroll
            for (int np = 0; np < 2; np++) {
                int n = warpN * 32 + np * 16 + l16;
                ldsm4(bfr[2 * np][0], bfr[2 * np + 1][0],
                      bfr[2 * np][1], bfr[2 * np + 1][1],
                      &Bs[cur][n][kk0 + lhi]);
            }
#pragma unroll
            for (int mt = 0; mt < 4; mt++)
#pragma unroll
                for (int nt = 0; nt < 4; nt++)
                    mma_bf16(acc[mt][nt], af[mt], bfr[nt]);
        }
        __syncthreads();
    }

#pragma unroll
    for (int mt = 0; mt < 4; mt++) {
        int r0 = bm + warpM * 64 + mt * 16 + g;
#pragma unroll
        for (int nt = 0; nt < 4; nt++) {
            int c = bn + warpN * 32 + nt * 8 + 2 * tig;
            float2 bv = *(const float2*)&bias[c];
            float v0 = acc[mt][nt][0] + bv.x;
            float v1 = acc[mt][nt][1] + bv.y;
            float v2 = acc[mt][nt][2] + bv.x;
            float v3 = acc[mt][nt][3] + bv.y;
            if (EP == EP_BIAS_GELU) {
                v0 = 0.5f * v0 * (1.f + erff(v0 * 0.70710678118654752f));
                v1 = 0.5f * v1 * (1.f + erff(v1 * 0.70710678118654752f));
                v2 = 0.5f * v2 * (1.f + erff(v2 * 0.70710678118654752f));
                v3 = 0.5f * v3 * (1.f + erff(v3 * 0.70710678118654752f));
            }
            if (EP == EP_BIAS_RES) {
                float2 r0v = *(const float2*)&res[(size_t)r0 * N + c];
                float2 r1v = *(const float2*)&res[(size_t)(r0 + 8) * N + c];
                v0 += r0v.x; v1 += r0v.y; v2 += r1v.x; v3 += r1v.y;
            }
            if (sizeof(OutT) == 2) {
                *(bf162*)((bf16*)C + (size_t)r0 * N + c) = __floats2bfloat162_rn(v0, v1);
                *(bf162*)((bf16*)C + (size_t)(r0 + 8) * N + c) = __floats2bfloat162_rn(v2, v3);
            } else {
                *(float2*)((float*)C + (size_t)r0 * N + c) = make_float2(v0, v1);
                *(float2*)((float*)C + (size_t)(r0 + 8) * N + c) = make_float2(v2, v3);
            }
        }
    }
}

// ---------------- fused proj + residual + LN2: one block per 128 rows ------
// x1 = o @ wp^T + proj_b + x  (fp32, stored)
// z  = LN(x1) * g2 + b2       (bf16, stored)
// Tile 128x256 (full rows), 512 threads, warp grid 4Mx4N, warp tile 32x64.
#define PJ_SMEM (20480 + 40960 + 4096 + 512 + 512 + 1024 + 1024)
__global__ __launch_bounds__(512, 1) void proj_ln2(const bf16* __restrict__ A,
                                                   const bf16* __restrict__ W,
                                                   const float* __restrict__ bias,
                                                   const float* __restrict__ res,
                                                   float* __restrict__ X1,
                                                   const float* __restrict__ g2,
                                                   const float* __restrict__ b2,
                                                   bf16* __restrict__ Z) {
    extern __shared__ char dsm[];
    bf16*  AsB   = (bf16*)dsm;                    // 2 stages x 128 x SP40
    bf16*  BsB   = (bf16*)(dsm + 20480);          // 2 stages x 256 x SP40
    float* sstat = (float*)(dsm + 61440);         // [4][128][2]
    float* srm   = (float*)(dsm + 65536);         // [128]
    float* sri   = (float*)(dsm + 66048);         // [128]
    float* sg2   = (float*)(dsm + 66560);         // [256]
    float* sb2   = (float*)(dsm + 67584);         // [256]

    const int K = 256, N = 256;
    int tid = threadIdx.x;
    int bm = blockIdx.x * 128;
    int warp = tid >> 5, lane = tid & 31;
    int g = lane >> 2, tig = lane & 3;
    int warpM = warp >> 2, warpN = warp & 3;      // 4 x 4
    int l16 = lane & 15, lhi = (lane >> 4) * 8;

    for (int i = tid; i < 256; i += 512) { sg2[i] = g2[i]; sb2[i] = b2[i]; }

    int lrA = tid >> 2, lcA = (tid & 3) * 8;      // A: 128 rows x 4 chunks
    int lrB = tid >> 1, lcB = (tid & 1) * 16;     // B: 256 rows x 2 chunks/thread

    const bf16* Aptr = A + (size_t)(bm + lrA) * K + lcA;
    const bf16* Wptr = W + (size_t)lrB * K;

    float acc[2][8][4];
#pragma unroll
    for (int i = 0; i < 2; i++)
#pragma unroll
        for (int j = 0; j < 8; j++)
#pragma unroll
            for (int t = 0; t < 4; t++) acc[i][j][t] = 0.f;

    // prologue: stage 0 (R7 ordering preserved in mainloop)
    cpa16(&AsB[lrA * SP40 + lcA], Aptr);
    cpa16(&BsB[lrB * SP40 + lcB],     Wptr + lcB);
    cpa16(&BsB[lrB * SP40 + lcB + 8], Wptr + lcB + 8);
    asm volatile("cp.async.commit_group;\n");

    for (int it = 0; it < 8; it++) {
        int cur = it & 1;
        bf16* Asc = AsB + cur * (128 * SP40);
        bf16* Bsc = BsB + cur * (256 * SP40);
        if (it + 1 < 8) {
            int k0 = (it + 1) * 32;
            int nxt = cur ^ 1;
            cpa16(AsB + nxt * (128 * SP40) + lrA * SP40 + lcA, Aptr + k0);
            cpa16(BsB + nxt * (256 * SP40) + lrB * SP40 + lcB,     Wptr + k0 + lcB);
            cpa16(BsB + nxt * (256 * SP40) + lrB * SP40 + lcB + 8, Wptr + k0 + lcB + 8);
            asm volatile("cp.async.commit_group;\n");
            asm volatile("cp.async.wait_group 1;\n");
        } else {
            asm volatile("cp.async.wait_group 0;\n");
        }
        __syncthreads();

#pragma unroll
        for (int s = 0; s < 2; s++) {
            int kk0 = s * 16;
            unsigned af[2][4], bfr[8][2];
#pragma unroll
            for (int mt = 0; mt < 2; mt++) {
                int m = warpM * 32 + mt * 16 + l16;
                ldsm4(af[mt][0], af[mt][1], af[mt][2], af[mt][3],
                      &Asc[m * SP40 + kk0 + lhi]);
            }
#pragma unroll
            for (int np = 0; np < 4; np++) {
                int n = warpN * 64 + np * 16 + l16;
                ldsm4(bfr[2 * np][0], bfr[2 * np + 1][0],
                      bfr[2 * np][1], bfr[2 * np + 1][1],
                      &Bsc[n * SP40 + kk0 + lhi]);
            }
#pragma unroll
            for (int mt = 0; mt < 2; mt++)
#pragma unroll
                for (int nt = 0; nt < 8; nt++)
                    mma_bf16(acc[mt][nt], af[mt], bfr[nt]);
        }
        __syncthreads();
    }

    // ---- epilogue: x1 = acc + bias + res, store fp32, gather LN stats -----
    float psum[2][2] = {{0.f, 0.f}, {0.f, 0.f}};
    float psq [2][2] = {{0.f, 0.f}, {0.f, 0.f}};
#pragma unroll
    for (int mt = 0; mt < 2; mt++) {
        int r0 = bm + warpM * 32 + mt * 16 + g;
        int r1 = r0 + 8;
#pragma unroll
        for (int nt = 0; nt < 8; nt++) {
            int c = warpN * 64 + nt * 8 + 2 * tig;
            float2 bv = *(const float2*)&bias[c];
            float v0 = acc[mt][nt][0] + bv.x + res[(size_t)r0 * N + c];
            float v1 = acc[mt][nt][1] + bv.y + res[(size_t)r0 * N + c + 1];
            float v2 = acc[mt][nt][2] + bv.x + res[(size_t)r1 * N + c];
            float v3 = acc[mt][nt][3] + bv.y + res[(size_t)r1 * N + c + 1];
            *(float2*)&X1[(size_t)r0 * N + c] = make_float2(v0, v1);
            *(float2*)&X1[(size_t)r1 * N + c] = make_float2(v2, v3);
            acc[mt][nt][0] = v0; acc[mt][nt][1] = v1;
            acc[mt][nt][2] = v2; acc[mt][nt][3] = v3;
            psum[mt][0] += v0 + v1; psq[mt][0] += v0 * v0 + v1 * v1;
            psum[mt][1] += v2 + v3; psq[mt][1] += v2 * v2 + v3 * v3;
        }
    }
    // reduce over tig (4 lanes share a row)
#pragma unroll
    for (int mt = 0; mt < 2; mt++)
#pragma unroll
        for (int u = 0; u < 2; u++) {
            psum[mt][u] += __shfl_xor_sync(0xffffffffu, psum[mt][u], 1);
            psum[mt][u] += __shfl_xor_sync(0xffffffffu, psum[mt][u], 2);
            psq[mt][u]  += __shfl_xor_sync(0xffffffffu, psq[mt][u], 1);
            psq[mt][u]  += __shfl_xor_sync(0xffffffffu, psq[mt][u], 2);
        }
    if (tig == 0) {
#pragma unroll
        for (int mt = 0; mt < 2; mt++)
#pragma unroll
            for (int u = 0; u < 2; u++) {
                int rl = warpM * 32 + mt * 16 + u * 8 + g;
                sstat[(warpN * 128 + rl) * 2]     = psum[mt][u];
                sstat[(warpN * 128 + rl) * 2 + 1] = psq[mt][u];
            }
    }
    __syncthreads();
    if (tid < 128) {
        float S = 0.f, Q = 0.f;
#pragma unroll
        for (int w = 0; w < 4; w++) {
            S += sstat[(w * 128 + tid) * 2];
            Q += sstat[(w * 128 + tid) * 2 + 1];
        }
        float m = S * (1.f / 256.f);
        srm[tid] = m;
        sri[tid] = rsqrtf(Q * (1.f / 256.f) - m * m + 1e-5f);
    }
    __syncthreads();

    // ---- z = LN(x1) (bf16) -------------------------------------------------
#pragma unroll
    for (int mt = 0; mt < 2; mt++) {
        int rl0 = warpM * 32 + mt * 16 + g;
        int rl1 = rl0 + 8;
        float m0 = srm[rl0], i0 = sri[rl0];
        float m1 = srm[rl1], i1 = sri[rl1];
        int r0 = bm + rl0, r1 = bm + rl1;
#pragma unroll
        for (int nt = 0; nt < 8; nt++) {
            int c = warpN * 64 + nt * 8 + 2 * tig;
            float gA = sg2[c], gB = sg2[c + 1];
            float bA = sb2[c], bB = sb2[c + 1];
            bf162 z0 = __floats2bfloat162_rn((acc[mt][nt][0] - m0) * i0 * gA + bA,
                                             (acc[mt][nt][1] - m0) * i0 * gB + bB);
            bf162 z1 = __floats2bfloat162_rn((acc[mt][nt][2] - m1) * i1 * gA + bA,
                                             (acc[mt][nt][3] - m1) * i1 * gB + bB);
            *(bf162*)&Z[(size_t)r0 * N + c] = z0;
            *(bf162*)&Z[(size_t)r1 * N + c] = z1;
        }
    }
}

// ---------------- attention: 2 heads / block, P kept in registers ----------
#define QP 40
#define HSTR (3 * 64 * QP)
__global__ __launch_bounds__(256) void attn_mma(const bf16* __restrict__ qkv,
                                                const float* __restrict__ bias_full,
                                                bf16* __restrict__ o) {
    __shared__ bf16 smem[2 * HSTR];
    __shared__ int  TOF[64];

    int bw = blockIdx.x >> 2;
    int hp = blockIdx.x & 3;
    int b  = bw >> 6;
    int wi = bw & 63;
    int wh = wi >> 3;
    int ww = wi & 7;
    int tid  = threadIdx.x;
    int warp = tid >> 5, lane = tid & 31;
    int hl   = warp >> 2;
    int w4   = warp & 3;
    int g = lane >> 2, tig = lane & 3;
    int l16 = lane & 15;
    int lhi = (lane >> 4) * 8;

    bf16* SQ = smem + hl * HSTR;
    bf16* SK = SQ + 64 * QP;
    bf16* SV = SK + 64 * QP;

    if (tid < 64) {
        int n = tid;
        int r = n / 7, c = n - r * 7;
        TOF[n] = (n < 49) ? (b * 3136 + (wh * 7 + r) * 56 + ww * 7 + c) : 0;
    }
    __syncthreads();

    for (int idx = tid; idx < 512; idx += 256) {
        int n   = idx >> 3;
        int hl2 = (idx >> 2) & 1;
        int seg = (idx & 3) * 8;
        const bf16* base = qkv + (size_t)TOF[n] * 768 + hp * 64 + hl2 * 32 + seg;
        unsigned sz = (n < 49) ? 16u : 0u;
        bf16* SQh = smem + hl2 * HSTR;
        cpa16z(&SQh[n * QP + seg],            base,       sz);
        cpa16z(&SQh[64 * QP + n * QP + seg],  base + 256, sz);
        cpa16z(&SQh[128 * QP + n * QP + seg], base + 512, sz);
    }
    asm volatile("cp.async.commit_group;\n");
    asm volatile("cp.async.wait_group 0;\n");
    __syncthreads();

    float accS[8][4];
#pragma unroll
    for (int nt = 0; nt < 8; nt++)
#pragma unroll
        for (int t = 0; t < 4; t++) accS[nt][t] = 0.f;

    int wrow = w4 * 16;
#pragma unroll
    for (int ks = 0; ks < 2; ks++) {
        int kk0 = ks * 16;
        unsigned a[4];
        ldsm4(a[0], a[1], a[2], a[3], &SQ[(wrow + l16) * QP + kk0 + lhi]);
#pragma unroll
        for (int np = 0; np < 4; np++) {
            unsigned b0[4];
            ldsm4(b0[0], b0[1], b0[2], b0[3],
                  &SK[(np * 16 + l16) * QP + kk0 + lhi]);
            unsigned bf0[2] = { b0[0], b0[2] };
            unsigned bf1[2] = { b0[1], b0[3] };
            mma_bf16(accS[2 * np],     a, bf0);
            mma_bf16(accS[2 * np + 1], a, bf1);
        }
    }

    const float sc = 0.17677669529663687f;
    int head = hp * 2 + hl;
    int r0 = wrow + g, r1 = wrow + g + 8;
    const float* bh = bias_full + head * 4096;
    float m0 = -1e30f, m1 = -1e30f;
#pragma unroll
    for (int nt = 0; nt < 8; nt++) {
        float2 b0 = *(const float2*)(bh + r0 * 64 + nt * 8 + 2 * tig);
        float2 b1 = *(const float2*)(bh + r1 * 64 + nt * 8 + 2 * tig);
        accS[nt][0] = accS[nt][0] * sc + b0.x;
        accS[nt][1] = accS[nt][1] * sc + b0.y;
        accS[nt][2] = accS[nt][2] * sc + b1.x;
        accS[nt][3] = accS[nt][3] * sc + b1.y;
        m0 = fmaxf(m0, fmaxf(accS[nt][0], accS[nt][1]));
        m1 = fmaxf(m1, fmaxf(accS[nt][2], accS[nt][3]));
    }
    m0 = fmaxf(m0, __shfl_xor_sync(0xffffffffu, m0, 1));
    m0 = fmaxf(m0, __shfl_xor_sync(0xffffffffu, m0, 2));
    m1 = fmaxf(m1, __shfl_xor_sync(0xffffffffu, m1, 1));
    m1 = fmaxf(m1, __shfl_xor_sync(0xffffffffu, m1, 2));

    float s0 = 0.f, s1 = 0.f;
#pragma unroll
    for (int nt = 0; nt < 8; nt++) {
        accS[nt][0] = __expf(accS[nt][0] - m0);
        accS[nt][1] = __expf(accS[nt][1] - m0);
        accS[nt][2] = __expf(accS[nt][2] - m1);
        accS[nt][3] = __expf(accS[nt][3] - m1);
        s0 += accS[nt][0] + accS[nt][1];
        s1 += accS[nt][2] + accS[nt][3];
    }
    s0 += __shfl_xor_sync(0xffffffffu, s0, 1);
    s0 += __shfl_xor_sync(0xffffffffu, s0, 2);
    s1 += __shfl_xor_sync(0xffffffffu, s1, 1);
    s1 += __shfl_xor_sync(0xffffffffu, s1, 2);
    float i0 = 1.f / s0, i1 = 1.f / s1;

    unsigned pu[8], pl[8];
#pragma unroll
    for (int nt = 0; nt < 8; nt++) {
        bf162 u = __floats2bfloat162_rn(accS[nt][0] * i0, accS[nt][1] * i0);
        bf162 l = __floats2bfloat162_rn(accS[nt][2] * i1, accS[nt][3] * i1);
        pu[nt] = *(unsigned*)&u;
        pl[nt] = *(unsigned*)&l;
    }

    float accO[4][4];
#pragma unroll
    for (int nt = 0; nt < 4; nt++)
#pragma unroll
        for (int t = 0; t < 4; t++) accO[nt][t] = 0.f;

    int vrow_l = (lane & 7) + ((lane >> 4) & 1) * 8;
    int vcol_l = ((lane >> 3) & 1) * 8;
#pragma unroll
    for (int ks = 0; ks < 4; ks++) {
        int kb = ks * 16;
        unsigned a[4] = { pu[2 * ks], pl[2 * ks], pu[2 * ks + 1], pl[2 * ks + 1] };
#pragma unroll
        for (int np = 0; np < 2; np++) {
            unsigned b0[4];
            ldsm4t(b0[0], b0[1], b0[2], b0[3],
                   &SV[(kb + vrow_l) * QP + np * 16 + vcol_l]);
            unsigned bf0[2] = { b0[0], b0[2] };
            unsigned bf1[2] = { b0[1], b0[3] };
            mma_bf16(accO[2 * np],     a, bf0);
            mma_bf16(accO[2 * np + 1], a, bf1);
        }
    }

    if (r0 < 49) {
        bf16* op = o + (size_t)TOF[r0] * 256 + head * 32;
#pragma unroll
        for (int nt = 0; nt < 4; nt++)
            *(bf162*)(op + nt * 8 + 2 * tig) = __floats2bfloat162_rn(accO[nt][0], accO[nt][1]);
    }
    if (r1 < 49) {
        bf16* op = o + (size_t)TOF[r1] * 256 + head * 32;
#pragma unroll
        for (int nt = 0; nt < 4; nt++)
            *(bf162*)(op + nt * 8 + 2 * tig) = __floats2bfloat162_rn(accO[nt][2], accO[nt][3]);
    }
}

// ---------------- launch ----------------
extern "C" void kernel_launch(void* const* d_in, const int* in_sizes, int n_in,
                              void* d_out, int out_size) {
    const float* x          = (const float*)d_in[0];
    const float* norm1_g    = (const float*)d_in[1];
    const float* norm1_b    = (const float*)d_in[2];
    const float* qkv_w      = (const float*)d_in[3];
    const float* qkv_b      = (const float*)d_in[4];
    const float* bias_table = (const float*)d_in[5];
    const float* proj_w     = (const float*)d_in[6];
    const float* proj_b     = (const float*)d_in[7];
    const float* norm2_g    = (const float*)d_in[8];
    const float* norm2_b    = (const float*)d_in[9];
    const float* ffn_w1     = (const float*)d_in[10];
    const float* ffn_b1     = (const float*)d_in[11];
    const float* ffn_w2     = (const float*)d_in[12];
    const float* ffn_b2     = (const float*)d_in[13];
    float* out = (float*)d_out;

    bf16 *y, *qkv, *o, *z, *h1, *wq, *wp, *w1, *w2;
    float *x1, *bf;
    cudaGetSymbolAddress((void**)&y,   g_y);
    cudaGetSymbolAddress((void**)&qkv, g_qkv);
    cudaGetSymbolAddress((void**)&o,   g_o);
    cudaGetSymbolAddress((void**)&x1,  g_x1);
    cudaGetSymbolAddress((void**)&z,   g_z);
    cudaGetSymbolAddress((void**)&h1,  g_h1);
    cudaGetSymbolAddress((void**)&bf,  g_bias);
    cudaGetSymbolAddress((void**)&wq,  g_wq);
    cudaGetSymbolAddress((void**)&wp,  g_wp);
    cudaGetSymbolAddress((void**)&w1,  g_w1);
    cudaGetSymbolAddress((void**)&w2,  g_w2);

    const int MT = TOK;  // 100352 = 784*128

    cudaFuncSetAttribute(proj_ln2,
                         cudaFuncAttributeMaxDynamicSharedMemorySize, PJ_SMEM);

    pre_ln1<<<PRE_BLKS + TOK / 8, 256>>>(qkv_w, proj_w, ffn_w1, ffn_w2, bias_table,
                                         wq, wp, w1, w2, bf,
                                         x, norm1_g, norm1_b, y);

    hgemm<EP_BIAS, bf16><<<dim3(768 / 128, MT / 128), 256>>>(y, wq, qkv_b, nullptr,
                                                             qkv, MT, 768, 256);

    attn_mma<<<NWIN * 4, 256>>>(qkv, bf, o);

    // fused proj + residual + LN2 -> x1 (fp32) and z (bf16)
    proj_ln2<<<MT / 128, 512, PJ_SMEM>>>(o, wp, proj_b, x, x1,
                                         norm2_g, norm2_b, z);

    hgemm<EP_BIAS_GELU, bf16><<<dim3(HID / 128, MT / 128), 256>>>(z, w1, ffn_b1, nullptr,
                                                                  h1, MT, HID, 256);

    hgemm<EP_BIAS_RES, float><<<dim3(256 / 128, MT / 128), 256>>>(h1, w2, ffn_b2, x1,
                                                                  out, MT, 256, 1024);
}

// round 17
// speedup vs baseline: 1.0051x; 1.0051x over previous
#include <cuda_runtime.h>
#include <cuda_bf16.h>
#include <cstdint>
#include <math.h>

// ---------------- problem constants ----------------
#define NB 32
#define HH 56
#define WW 56
#define CD 256
#define TOK (NB*HH*WW)          // 100352 tokens
#define HEADS 8
#define HDIM 32
#define HID 1024
#define WS 7
#define NWIN (TOK/(WS*WS))      // 2048 windows

typedef __nv_bfloat16 bf16;
typedef __nv_bfloat162 bf162;

// ---------------- scratch (static device globals; no runtime alloc) -------
__device__ __align__(16) bf16  g_y   [(size_t)TOK * CD];
__device__ __align__(16) bf16  g_qkv [(size_t)TOK * 3 * CD];
__device__ __align__(16) bf16  g_o   [(size_t)TOK * CD];
__device__ __align__(16) float g_x1  [(size_t)TOK * CD];
__device__ __align__(16) bf16  g_z   [(size_t)TOK * CD];
__device__ __align__(16) bf16  g_h1  [(size_t)TOK * HID];
__device__ __align__(16) float g_bias[8 * 64 * 64];
__device__ __align__(16) bf16  g_wq[3 * CD * CD];
__device__ __align__(16) bf16  g_wp[CD * CD];
__device__ __align__(16) bf16  g_w1[HID * CD];
__device__ __align__(16) bf16  g_w2[CD * HID];

// ---------------- fused preprocessing + LN1 ---------------------------------
#define PRE_BLKS 896
__global__ __launch_bounds__(256) void pre_ln1(const float* __restrict__ qkv_w,
                                               const float* __restrict__ proj_w,
                                               const float* __restrict__ ffn_w1,
                                               const float* __restrict__ ffn_w2,
                                               const float* __restrict__ table,
                                               bf16* __restrict__ wq, bf16* __restrict__ wp,
                                               bf16* __restrict__ w1, bf16* __restrict__ w2,
                                               float* __restrict__ bfull,
                                               const float* __restrict__ x,
                                               const float* __restrict__ lng,
                                               const float* __restrict__ lnb,
                                               bf16* __restrict__ y) {
    if (blockIdx.x < PRE_BLKS) {
        int i = blockIdx.x * 256 + threadIdx.x;
        if (i < 196608) {
            const float* src;
            bf16* dst;
            int j;
            if (i < 49152)        { src = qkv_w;  dst = wq; j = i; }
            else if (i < 65536)   { src = proj_w; dst = wp; j = i - 49152; }
            else if (i < 131072)  { src = ffn_w1; dst = w1; j = i - 65536; }
            else                  { src = ffn_w2; dst = w2; j = i - 131072; }
            float4 v = ((const float4*)src)[j];
            *(bf162*)&dst[j * 4]     = __floats2bfloat162_rn(v.x, v.y);
            *(bf162*)&dst[j * 4 + 2] = __floats2bfloat162_rn(v.z, v.w);
        } else if (i < 229376) {
            int idx = i - 196608;
            int h = idx >> 12;
            int r = (idx >> 6) & 63;
            int c = idx & 63;
            float v;
            if (c >= 49) v = -1e30f;
            else if (r >= 49) v = 0.f;
            else {
                int ri = r / 7, ci = r % 7, rj = c / 7, cj = c % 7;
                int rel = (ri - rj + 6) * 13 + (ci - cj + 6);
                v = table[rel * 8 + h];
            }
            bfull[idx] = v;
        }
        return;
    }
    int warp = ((blockIdx.x - PRE_BLKS) * 256 + threadIdx.x) >> 5;
    int lane = threadIdx.x & 31;
    if (warp >= TOK) return;
    const float* row = x + (size_t)warp * CD;
    float v[8];
    *(float4*)&v[0] = ((const float4*)row)[lane * 2];
    *(float4*)&v[4] = ((const float4*)row)[lane * 2 + 1];
    float s = 0.f;
#pragma unroll
    for (int k = 0; k < 8; k++) s += v[k];
#pragma unroll
    for (int o = 16; o; o >>= 1) s += __shfl_xor_sync(0xffffffffu, s, o);
    float mean = s * (1.f / 256.f);
    float ss = 0.f;
#pragma unroll
    for (int k = 0; k < 8; k++) { float d = v[k] - mean; ss += d * d; }
#pragma unroll
    for (int o = 16; o; o >>= 1) ss += __shfl_xor_sync(0xffffffffu, ss, o);
    float inv = rsqrtf(ss * (1.f / 256.f) + 1e-5f);
    float gg[8], bb[8];
    *(float4*)&gg[0] = ((const float4*)lng)[lane * 2];
    *(float4*)&gg[4] = ((const float4*)lng)[lane * 2 + 1];
    *(float4*)&bb[0] = ((const float4*)lnb)[lane * 2];
    *(float4*)&bb[4] = ((const float4*)lnb)[lane * 2 + 1];
    bf16* orow = y + (size_t)warp * CD + lane * 8;
#pragma unroll
    for (int k = 0; k < 4; k++) {
        float v0 = (v[2*k]   - mean) * inv * gg[2*k]   + bb[2*k];
        float v1 = (v[2*k+1] - mean) * inv * gg[2*k+1] + bb[2*k+1];
        *(bf162*)&orow[2*k] = __floats2bfloat162_rn(v0, v1);
    }
}

// ---------------- LayerNorm: warp per token, bf16 out ----------------------
__global__ __launch_bounds__(256) void ln_kernel(const float* __restrict__ in,
                                                 const float* __restrict__ g,
                                                 const float* __restrict__ b,
                                                 bf16* __restrict__ out) {
    int warp = (blockIdx.x * blockDim.x + threadIdx.x) >> 5;
    int lane = threadIdx.x & 31;
    if (warp >= TOK) return;
    const float* row = in + (size_t)warp * CD;
    float v[8];
    *(float4*)&v[0] = ((const float4*)row)[lane * 2];
    *(float4*)&v[4] = ((const float4*)row)[lane * 2 + 1];
    float s = 0.f;
#pragma unroll
    for (int k = 0; k < 8; k++) s += v[k];
#pragma unroll
    for (int o = 16; o; o >>= 1) s += __shfl_xor_sync(0xffffffffu, s, o);
    float mean = s * (1.f / 256.f);
    float ss = 0.f;
#pragma unroll
    for (int k = 0; k < 8; k++) { float d = v[k] - mean; ss += d * d; }
#pragma unroll
    for (int o = 16; o; o >>= 1) ss += __shfl_xor_sync(0xffffffffu, ss, o);
    float inv = rsqrtf(ss * (1.f / 256.f) + 1e-5f);
    float gg[8], bb[8];
    *(float4*)&gg[0] = ((const float4*)g)[lane * 2];
    *(float4*)&gg[4] = ((const float4*)g)[lane * 2 + 1];
    *(float4*)&bb[0] = ((const float4*)b)[lane * 2];
    *(float4*)&bb[4] = ((const float4*)b)[lane * 2 + 1];
    bf16* orow = out + (size_t)warp * CD + lane * 8;
#pragma unroll
    for (int k = 0; k < 4; k++) {
        float v0 = (v[2*k]   - mean) * inv * gg[2*k]   + bb[2*k];
        float v1 = (v[2*k+1] - mean) * inv * gg[2*k+1] + bb[2*k+1];
        *(bf162*)&orow[2*k] = __floats2bfloat162_rn(v0, v1);
    }
}

// ---------------- mma / cp.async / ldmatrix helpers ------------------------
__device__ __forceinline__ void mma_bf16(float* c, const unsigned* a, const unsigned* b) {
    asm volatile(
        "mma.sync.aligned.m16n8k16.row.col.f32.bf16.bf16.f32 "
        "{%0,%1,%2,%3}, {%4,%5,%6,%7}, {%8,%9}, {%0,%1,%2,%3};\n"
        : "+f"(c[0]), "+f"(c[1]), "+f"(c[2]), "+f"(c[3])
        : "r"(a[0]), "r"(a[1]), "r"(a[2]), "r"(a[3]), "r"(b[0]), "r"(b[1]));
}

__device__ __forceinline__ void cpa16(void* smem_dst, const void* gsrc) {
    unsigned s = (unsigned)__cvta_generic_to_shared(smem_dst);
    asm volatile("cp.async.cg.shared.global [%0], [%1], 16;\n" :: "r"(s), "l"(gsrc));
}

__device__ __forceinline__ void cpa16z(void* smem_dst, const void* gsrc, unsigned srcsz) {
    unsigned s = (unsigned)__cvta_generic_to_shared(smem_dst);
    asm volatile("cp.async.cg.shared.global [%0], [%1], 16, %2;\n"
                 :: "r"(s), "l"(gsrc), "r"(srcsz));
}

__device__ __forceinline__ void ldsm4(unsigned& r0, unsigned& r1,
                                      unsigned& r2, unsigned& r3, const void* p) {
    unsigned a = (unsigned)__cvta_generic_to_shared(p);
    asm volatile("ldmatrix.sync.aligned.m8n8.x4.shared.b16 {%0,%1,%2,%3}, [%4];"
                 : "=r"(r0), "=r"(r1), "=r"(r2), "=r"(r3) : "r"(a));
}

__device__ __forceinline__ void ldsm4t(unsigned& r0, unsigned& r1,
                                       unsigned& r2, unsigned& r3, const void* p) {
    unsigned a = (unsigned)__cvta_generic_to_shared(p);
    asm volatile("ldmatrix.sync.aligned.m8n8.x4.trans.shared.b16 {%0,%1,%2,%3}, [%4];"
                 : "=r"(r0), "=r"(r1), "=r"(r2), "=r"(r3) : "r"(a));
}

// ---------------- bf16 GEMM (R7/R12-proven structure, FROZEN) --------------
enum { EP_BIAS = 0, EP_BIAS_RES = 1, EP_BIAS_GELU = 2 };

#define SP40 40   // smem pitch (halves): 8 rows @ stride 20 banks partition 32 banks

template <int EP, typename OutT>
__global__ __launch_bounds__(256) void hgemm(const bf16* __restrict__ A,
                                             const bf16* __restrict__ W,
                                             const float* __restrict__ bias,
                                             const float* __restrict__ res,
                                             OutT* __restrict__ C,
                                             int M, int N, int K) {
    __shared__ bf16 As[2][128][SP40];
    __shared__ bf16 Bs[2][128][SP40];

    int tid = threadIdx.x;
    int bm = blockIdx.y * 128;
    int bn = blockIdx.x * 128;
    int warp = tid >> 5, lane = tid & 31;
    int g = lane >> 2, tig = lane & 3;
    int warpM = warp >> 2;
    int warpN = warp & 3;
    int l16 = lane & 15;
    int lhi = (lane >> 4) * 8;

    int lrow = tid >> 2;
    int lcol = (tid & 3) * 8;

    const bf16* Aptr = A + (size_t)(bm + lrow) * K + lcol;
    const bf16* Wptr = W + (size_t)(bn + lrow) * K + lcol;

    float acc[4][4][4];
#pragma unroll
    for (int i = 0; i < 4; i++)
#pragma unroll
        for (int j = 0; j < 4; j++)
#pragma unroll
            for (int t = 0; t < 4; t++) acc[i][j][t] = 0.f;

    cpa16(&As[0][lrow][lcol],      Aptr);
    cpa16(&As[0][lrow + 64][lcol], Aptr + (size_t)64 * K);
    cpa16(&Bs[0][lrow][lcol],      Wptr);
    cpa16(&Bs[0][lrow + 64][lcol], Wptr + (size_t)64 * K);
    asm volatile("cp.async.commit_group;\n");

    int niter = K / 32;
    for (int it = 0; it < niter; it++) {
        int cur = it & 1;
        if (it + 1 < niter) {
            int k0 = (it + 1) * 32;
            int nxt = cur ^ 1;
            cpa16(&As[nxt][lrow][lcol],      Aptr + k0);
            cpa16(&As[nxt][lrow + 64][lcol], Aptr + (size_t)64 * K + k0);
            cpa16(&Bs[nxt][lrow][lcol],      Wptr + k0);
            cpa16(&Bs[nxt][lrow + 64][lcol], Wptr + (size_t)64 * K + k0);
            asm volatile("cp.async.commit_group;\n");
            asm volatile("cp.async.wait_group 1;\n");
        } else {
            asm volatile("cp.async.wait_group 0;\n");
        }
        __syncthreads();

#pragma unroll
        for (int s = 0; s < 2; s++) {
            int kk0 = s * 16;
            unsigned af[4][4], bfr[4][2];
#pragma unroll
            for (int mt = 0; mt < 4; mt++) {
                int m = warpM * 64 + mt * 16 + l16;
                ldsm4(af[mt][0], af[mt][1], af[mt][2], af[mt][3],
                      &As[cur][m][kk0 + lhi]);
            }
#pragma unroll
            for (int np = 0; np < 2; np++) {
                int n = warpN * 32 + np * 16 + l16;
                ldsm4(bfr[2 * np][0], bfr[2 * np + 1][0],
                      bfr[2 * np][1], bfr[2 * np + 1][1],
                      &Bs[cur][n][kk0 + lhi]);
            }
#pragma unroll
            for (int mt = 0; mt < 4; mt++)
#pragma unroll
                for (int nt = 0; nt < 4; nt++)
                    mma_bf16(acc[mt][nt], af[mt], bfr[nt]);
        }
        __syncthreads();
    }

#pragma unroll
    for (int mt = 0; mt < 4; mt++) {
        int r0 = bm + warpM * 64 + mt * 16 + g;
#pragma unroll
        for (int nt = 0; nt < 4; nt++) {
            int c = bn + warpN * 32 + nt * 8 + 2 * tig;
            float2 bv = *(const float2*)&bias[c];
            float v0 = acc[mt][nt][0] + bv.x;
            float v1 = acc[mt][nt][1] + bv.y;
            float v2 = acc[mt][nt][2] + bv.x;
            float v3 = acc[mt][nt][3] + bv.y;
            if (EP == EP_BIAS_GELU) {
                v0 = 0.5f * v0 * (1.f + erff(v0 * 0.70710678118654752f));
                v1 = 0.5f * v1 * (1.f + erff(v1 * 0.70710678118654752f));
                v2 = 0.5f * v2 * (1.f + erff(v2 * 0.70710678118654752f));
                v3 = 0.5f * v3 * (1.f + erff(v3 * 0.70710678118654752f));
            }
            if (EP == EP_BIAS_RES) {
                float2 r0v = *(const float2*)&res[(size_t)r0 * N + c];
                float2 r1v = *(const float2*)&res[(size_t)(r0 + 8) * N + c];
                v0 += r0v.x; v1 += r0v.y; v2 += r1v.x; v3 += r1v.y;
            }
            if (sizeof(OutT) == 2) {
                *(bf162*)((bf16*)C + (size_t)r0 * N + c) = __floats2bfloat162_rn(v0, v1);
                *(bf162*)((bf16*)C + (size_t)(r0 + 8) * N + c) = __floats2bfloat162_rn(v2, v3);
            } else {
                *(float2*)((float*)C + (size_t)r0 * N + c) = make_float2(v0, v1);
                *(float2*)((float*)C + (size_t)(r0 + 8) * N + c) = make_float2(v2, v3);
            }
        }
    }
}

// ---------------- attention: 2 heads / block, P in registers, inline idx ---
#define QP 40
#define HSTR (3 * 64 * QP)
__global__ __launch_bounds__(256) void attn_mma(const bf16* __restrict__ qkv,
                                                const float* __restrict__ bias_full,
                                                bf16* __restrict__ o) {
    __shared__ bf16 smem[2 * HSTR];

    int bw = blockIdx.x >> 2;
    int hp = blockIdx.x & 3;
    int b  = bw >> 6;
    int wi = bw & 63;
    int wh = wi >> 3;
    int ww = wi & 7;
    int tid  = threadIdx.x;
    int warp = tid >> 5, lane = tid & 31;
    int hl   = warp >> 2;
    int w4   = warp & 3;
    int g = lane >> 2, tig = lane & 3;
    int l16 = lane & 15;
    int lhi = (lane >> 4) * 8;

    int tbase = b * 3136 + wh * 7 * 56 + ww * 7;  // window origin token

    bf16* SQ = smem + hl * HSTR;
    bf16* SK = SQ + 64 * QP;
    bf16* SV = SK + 64 * QP;

    // ---- async load Q,K,V for both heads (zero-fill padded rows) ----------
#pragma unroll
    for (int rep = 0; rep < 2; rep++) {
        int idx = tid + rep * 256;
        int n   = idx >> 3;
        int hl2 = (idx >> 2) & 1;
        int seg = (idx & 3) * 8;
        int t   = (n < 49) ? (tbase + (n / 7) * 56 + (n % 7)) : 0;
        const bf16* base = qkv + (size_t)t * 768 + hp * 64 + hl2 * 32 + seg;
        unsigned sz = (n < 49) ? 16u : 0u;
        bf16* SQh = smem + hl2 * HSTR;
        cpa16z(&SQh[n * QP + seg],            base,       sz);
        cpa16z(&SQh[64 * QP + n * QP + seg],  base + 256, sz);
        cpa16z(&SQh[128 * QP + n * QP + seg], base + 512, sz);
    }
    asm volatile("cp.async.commit_group;\n");
    asm volatile("cp.async.wait_group 0;\n");
    __syncthreads();

    // ---- S = Q*K^T : warp does 16 rows x 64 cols of its head --------------
    float accS[8][4];
#pragma unroll
    for (int nt = 0; nt < 8; nt++)
#pragma unroll
        for (int t = 0; t < 4; t++) accS[nt][t] = 0.f;

    int wrow = w4 * 16;
#pragma unroll
    for (int ks = 0; ks < 2; ks++) {
        int kk0 = ks * 16;
        unsigned a[4];
        ldsm4(a[0], a[1], a[2], a[3], &SQ[(wrow + l16) * QP + kk0 + lhi]);
#pragma unroll
        for (int np = 0; np < 4; np++) {
            unsigned b0[4];
            ldsm4(b0[0], b0[1], b0[2], b0[3],
                  &SK[(np * 16 + l16) * QP + kk0 + lhi]);
            unsigned bf0[2] = { b0[0], b0[2] };
            unsigned bf1[2] = { b0[1], b0[3] };
            mma_bf16(accS[2 * np],     a, bf0);
            mma_bf16(accS[2 * np + 1], a, bf1);
        }
    }

    // ---- scale + bias + masked softmax (register-resident) ----------------
    const float sc = 0.17677669529663687f;
    int head = hp * 2 + hl;
    int r0 = wrow + g, r1 = wrow + g + 8;
    const float* bh = bias_full + head * 4096;
    float m0 = -1e30f, m1 = -1e30f;
#pragma unroll
    for (int nt = 0; nt < 8; nt++) {
        float2 b0 = *(const float2*)(bh + r0 * 64 + nt * 8 + 2 * tig);
        float2 b1 = *(const float2*)(bh + r1 * 64 + nt * 8 + 2 * tig);
        accS[nt][0] = accS[nt][0] * sc + b0.x;
        accS[nt][1] = accS[nt][1] * sc + b0.y;
        accS[nt][2] = accS[nt][2] * sc + b1.x;
        accS[nt][3] = accS[nt][3] * sc + b1.y;
        m0 = fmaxf(m0, fmaxf(accS[nt][0], accS[nt][1]));
        m1 = fmaxf(m1, fmaxf(accS[nt][2], accS[nt][3]));
    }
    m0 = fmaxf(m0, __shfl_xor_sync(0xffffffffu, m0, 1));
    m0 = fmaxf(m0, __shfl_xor_sync(0xffffffffu, m0, 2));
    m1 = fmaxf(m1, __shfl_xor_sync(0xffffffffu, m1, 1));
    m1 = fmaxf(m1, __shfl_xor_sync(0xffffffffu, m1, 2));

    float s0 = 0.f, s1 = 0.f;
#pragma unroll
    for (int nt = 0; nt < 8; nt++) {
        accS[nt][0] = __expf(accS[nt][0] - m0);
        accS[nt][1] = __expf(accS[nt][1] - m0);
        accS[nt][2] = __expf(accS[nt][2] - m1);
        accS[nt][3] = __expf(accS[nt][3] - m1);
        s0 += accS[nt][0] + accS[nt][1];
        s1 += accS[nt][2] + accS[nt][3];
    }
    s0 += __shfl_xor_sync(0xffffffffu, s0, 1);
    s0 += __shfl_xor_sync(0xffffffffu, s0, 2);
    s1 += __shfl_xor_sync(0xffffffffu, s1, 1);
    s1 += __shfl_xor_sync(0xffffffffu, s1, 2);
    float i0 = 1.f / s0, i1 = 1.f / s1;

    // ---- pack P directly into MMA A-fragments (C-frag == A-frag layout) ---
    unsigned pu[8], pl[8];
#pragma unroll
    for (int nt = 0; nt < 8; nt++) {
        bf162 u = __floats2bfloat162_rn(accS[nt][0] * i0, accS[nt][1] * i0);
        bf162 l = __floats2bfloat162_rn(accS[nt][2] * i1, accS[nt][3] * i1);
        pu[nt] = *(unsigned*)&u;
        pl[nt] = *(unsigned*)&l;
    }

    // ---- O = P * V : A from registers, B via ldmatrix.trans on V ----------
    float accO[4][4];
#pragma unroll
    for (int nt = 0; nt < 4; nt++)
#pragma unroll
        for (int t = 0; t < 4; t++) accO[nt][t] = 0.f;

    int vrow_l = (lane & 7) + ((lane >> 4) & 1) * 8;
    int vcol_l = ((lane >> 3) & 1) * 8;
#pragma unroll
    for (int ks = 0; ks < 4; ks++) {
        int kb = ks * 16;
        unsigned a[4] = { pu[2 * ks], pl[2 * ks], pu[2 * ks + 1], pl[2 * ks + 1] };
#pragma unroll
        for (int np = 0; np < 2; np++) {
            unsigned b0[4];
            ldsm4t(b0[0], b0[1], b0[2], b0[3],
                   &SV[(kb + vrow_l) * QP + np * 16 + vcol_l]);
            unsigned bf0[2] = { b0[0], b0[2] };
            unsigned bf1[2] = { b0[1], b0[3] };
            mma_bf16(accO[2 * np],     a, bf0);
            mma_bf16(accO[2 * np + 1], a, bf1);
        }
    }

    // ---- scatter O to token layout (inline token index) -------------------
    if (r0 < 49) {
        int t = tbase + (r0 / 7) * 56 + (r0 % 7);
        bf16* op = o + (size_t)t * 256 + head * 32;
#pragma unroll
        for (int nt = 0; nt < 4; nt++)
            *(bf162*)(op + nt * 8 + 2 * tig) = __floats2bfloat162_rn(accO[nt][0], accO[nt][1]);
    }
    if (r1 < 49) {
        int t = tbase + (r1 / 7) * 56 + (r1 % 7);
        bf16* op = o + (size_t)t * 256 + head * 32;
#pragma unroll
        for (int nt = 0; nt < 4; nt++)
            *(bf162*)(op + nt * 8 + 2 * tig) = __floats2bfloat162_rn(accO[nt][2], accO[nt][3]);
    }
}

// ---------------- launch ----------------
extern "C" void kernel_launch(void* const* d_in, const int* in_sizes, int n_in,
                              void* d_out, int out_size) {
    const float* x          = (const float*)d_in[0];
    const float* norm1_g    = (const float*)d_in[1];
    const float* norm1_b    = (const float*)d_in[2];
    const float* qkv_w      = (const float*)d_in[3];
    const float* qkv_b      = (const float*)d_in[4];
    const float* bias_table = (const float*)d_in[5];
    const float* proj_w     = (const float*)d_in[6];
    const float* proj_b     = (const float*)d_in[7];
    const float* norm2_g    = (const float*)d_in[8];
    const float* norm2_b    = (const float*)d_in[9];
    const float* ffn_w1     = (const float*)d_in[10];
    const float* ffn_b1     = (const float*)d_in[11];
    const float* ffn_w2     = (const float*)d_in[12];
    const float* ffn_b2     = (const float*)d_in[13];
    float* out = (float*)d_out;

    bf16 *y, *qkv, *o, *z, *h1, *wq, *wp, *w1, *w2;
    float *x1, *bf;
    cudaGetSymbolAddress((void**)&y,   g_y);
    cudaGetSymbolAddress((void**)&qkv, g_qkv);
    cudaGetSymbolAddress((void**)&o,   g_o);
    cudaGetSymbolAddress((void**)&x1,  g_x1);
    cudaGetSymbolAddress((void**)&z,   g_z);
    cudaGetSymbolAddress((void**)&h1,  g_h1);
    cudaGetSymbolAddress((void**)&bf,  g_bias);
    cudaGetSymbolAddress((void**)&wq,  g_wq);
    cudaGetSymbolAddress((void**)&wp,  g_wp);
    cudaGetSymbolAddress((void**)&w1,  g_w1);
    cudaGetSymbolAddress((void**)&w2,  g_w2);

    const int MT = TOK;  // 100352 = 784*128

    pre_ln1<<<PRE_BLKS + TOK / 8, 256>>>(qkv_w, proj_w, ffn_w1, ffn_w2, bias_table,
                                         wq, wp, w1, w2, bf,
                                         x, norm1_g, norm1_b, y);

    hgemm<EP_BIAS, bf16><<<dim3(768 / 128, MT / 128), 256>>>(y, wq, qkv_b, nullptr,
                                                             qkv, MT, 768, 256);

    attn_mma<<<NWIN * 4, 256>>>(qkv, bf, o);

    hgemm<EP_BIAS_RES, float><<<dim3(256 / 128, MT / 128), 256>>>(o, wp, proj_b, x,
                                                                  x1, MT, 256, 256);

    ln_kernel<<<TOK / 8, 256>>>(x1, norm2_g, norm2_b, z);

    hgemm<EP_BIAS_GELU, bf16><<<dim3(HID / 128, MT / 128), 256>>>(z, w1, ffn_b1, nullptr,
                                                                  h1, MT, HID, 256);

    hgemm<EP_BIAS_RES, float><<<dim3(256 / 128, MT / 128), 256>>>(h1, w2, ffn_b2, x1,
                                                                  out, MT, 256, 1024);
}